// round 14
// baseline (speedup 1.0000x reference)
#include <cuda_runtime.h>

// QueryEncDec: 2x128-layer scalar GRU (H=in=1), T=256, fused 256-layer wavefront.
// v14: pipeline split across a 2-CTA CLUSTER (1 warp per SMSP -> no co-warp
// MUFU/issue contention). CTA0 = groups 0-3, CTA1 = groups 4-7.
//  - intra-CTA boundaries: named-barrier rendezvous per 8-step chunk (proven)
//  - cross-CTA boundary (3->4): DSMEM write-once inbox + 32 per-chunk
//    mbarriers (arrive = cluster release, wait = acquire; no parity reuse)
// Rotating shuffle + steady-state specialization retained from v12/v13.
//
// out[0:256]   = dec_out  (layer 255 output at each t)
// out[256:384] = dec_h    (final hidden of global layers 128..255)

#define GRU_T 256
#define KC    8
#define NCH   36     // 36*8 = 288 >= 287 inner steps

__device__ __forceinline__ float ftanh(float a) {
    float r; asm("tanh.approx.f32 %0, %1;" : "=f"(r) : "f"(a)); return r;
}
__device__ __forceinline__ unsigned smem_u32(const void* p) {
    return (unsigned)__cvta_generic_to_shared(p);
}
__device__ __forceinline__ unsigned mapa_rank(unsigned local, int rank) {
    unsigned rem;
    asm("mapa.shared::cluster.u32 %0, %1, %2;" : "=r"(rem) : "r"(local), "r"(rank));
    return rem;
}
__device__ __forceinline__ void st_remote_f32(unsigned addr, float v) {
    asm volatile("st.shared::cluster.f32 [%0], %1;" :: "r"(addr), "f"(v) : "memory");
}
__device__ __forceinline__ void mbar_arrive_remote(unsigned addr) {
    asm volatile("mbarrier.arrive.shared::cluster.b64 _, [%0];" :: "r"(addr) : "memory");
}
__device__ __forceinline__ void mbar_wait_phase0(unsigned addr) {
    asm volatile(
        "{\n\t.reg .pred P;\n"
        "WAITL_%=:\n\t"
        "mbarrier.try_wait.parity.acquire.cluster.shared::cta.b64 P, [%0], %1, 0x989680;\n\t"
        "@!P bra WAITL_%=;\n\t}"
        :: "r"(addr), "r"(0) : "memory");
}

struct GruW {
    float hwi_r, hwh_r, hb_r;
    float hwi_z, hwh_z, hb_z;
    float wi_n,  bi_n,  hwh_n, hbh_n;
};

template<bool STEADY>
__device__ __forceinline__ void run_chunk(
    int ic, int w, int lane, int l,
    bool mbar_wait, bool bar_pub, bool mbar_pub, bool remote_sink,
    const float* __restrict__ inbox, float* __restrict__ sink,
    unsigned rem_xb, unsigned rem_mbar, unsigned mbar_base,
    float* __restrict__ out, const GruW& W,
    float& h, float& val, float& nc_r, float& nc_z, float& ghn_h, float& hhalf)
{
    // ---- consumer side ----
    if (ic < GRU_T / KC) {
        if (mbar_wait) {
            if (lane == 31) mbar_wait_phase0(mbar_base + 8u * ic);
        } else if (w > 0) {
            asm volatile("bar.sync %0, %1;" :: "r"(w), "r"(64) : "memory");
        }
    }
    float pf[KC];
    if (lane == 31 && ic < GRU_T / KC) {
        float4 va = *(const float4*)(inbox + ic * KC);
        float4 vb = *(const float4*)(inbox + ic * KC + 4);
        pf[0]=va.x; pf[1]=va.y; pf[2]=va.z; pf[3]=va.w;
        pf[4]=vb.x; pf[5]=vb.y; pf[6]=vb.z; pf[7]=vb.w;
    }

    const int src = (lane + 31) & 31;      // rotation: lane0 <- lane31

    #pragma unroll
    for (int u = 0; u < KC; ++u) {
        const int j = ic * KC + u;
        const int t = j - lane;

        if (lane == 31) val = pf[u];       // off-chain inbox injection

        const float x = __shfl_sync(0xFFFFFFFFu, val, src, 32);

        const float t_r = ftanh(fmaf(W.hwi_r, x, nc_r));
        const float t_z = ftanh(fmaf(W.hwi_z, x, nc_z));
        const float xn  = fmaf(W.wi_n, x, W.bi_n);
        const float t_n = ftanh(fmaf(ghn_h, t_r, xn + ghn_h));
        const float A   = fmaf(-0.5f, t_z, 0.5f);
        const float C   = fmaf(hhalf, t_z, hhalf);
        const float hn  = fmaf(A, t_n, C);

        val = hn;
        if (STEADY) {
            h = hn;
            if (lane == 31) {
                if (remote_sink) st_remote_f32(rem_xb + 4u * t, h);
                else             sink[t] = h;
            }
        } else {
            const bool valid = (t >= 0) && (t < GRU_T);
            if (valid) h = hn;
            if (lane == 31 && valid) {
                if (remote_sink) st_remote_f32(rem_xb + 4u * t, h);
                else             sink[t] = h;
            }
            if (t == GRU_T - 1 && l >= 128) out[GRU_T + (l - 128)] = h; // dec_h
        }

        nc_r  = fmaf(W.hwh_r, h, W.hb_r);
        nc_z  = fmaf(W.hwh_z, h, W.hb_z);
        ghn_h = fmaf(W.hwh_n, h, W.hbh_n);
        hhalf = 0.5f * h;
    }

    // ---- producer side ----
    if (ic >= 4) {
        if (bar_pub) {
            asm volatile("bar.sync %0, %1;" :: "r"(w + 1), "r"(64) : "memory");
        } else if (mbar_pub) {
            if (lane == 31) mbar_arrive_remote(rem_mbar + 8u * (ic - 4));
        }
    }
}

__global__ __launch_bounds__(128, 1) __cluster_dims__(2, 1, 1)
void gru_wave_v14(const float* __restrict__ X,
                  const float* __restrict__ ewi, const float* __restrict__ ewh,
                  const float* __restrict__ ebi, const float* __restrict__ ebh,
                  const float* __restrict__ dwi, const float* __restrict__ dwh,
                  const float* __restrict__ dbi, const float* __restrict__ dbh,
                  float* __restrict__ out)
{
    const int tid  = threadIdx.x;          // 0..127
    const int w    = tid >> 5;             // local warp 0..3
    const int lane = tid & 31;

    unsigned rank;
    asm("mov.u32 %0, %%cluster_ctarank;" : "=r"(rank));

    const int G = (int)rank * 4 + w;       // global layer group 0..7
    const int l = G * 32 + lane;           // global layer 0..255

    __shared__ __align__(16) float xs[GRU_T];        // X (used by CTA0 g0)
    __shared__ __align__(16) float xb[GRU_T];        // cross-CTA inbox (CTA1)
    __shared__ __align__(16) float bb[3][GRU_T];     // intra-CTA boundaries
    __shared__ __align__(8)  unsigned long long mbar[GRU_T / KC];  // 32

    if (rank == 0) { xs[tid] = X[tid]; xs[tid + 128] = X[tid + 128]; }
    if (tid < GRU_T / KC) {
        unsigned a = smem_u32(&mbar[tid]);
        asm volatile("mbarrier.init.shared.b64 [%0], %1;" :: "r"(a), "r"(1) : "memory");
    }

    // per-layer scalar weights (torch gate order r,z,n)
    const bool  enc = (l < 128);
    const int   li  = enc ? l : (l - 128);
    const float* wi = enc ? ewi : dwi;
    const float* wh = enc ? ewh : dwh;
    const float* bi = enc ? ebi : dbi;
    const float* bh = enc ? ebh : dbh;

    const float wi_r = wi[li*3+0], wi_z = wi[li*3+1], wi_n = wi[li*3+2];
    const float wh_r = wh[li*3+0], wh_z = wh[li*3+1], wh_n = wh[li*3+2];
    const float bi_r = bi[li*3+0], bi_z = bi[li*3+1], bi_n = bi[li*3+2];
    const float bh_r = bh[li*3+0], bh_z = bh[li*3+1], bh_n = bh[li*3+2];

    GruW W;
    W.hwi_r = 0.5f * wi_r; W.hwh_r = 0.5f * wh_r; W.hb_r = 0.5f * (bi_r + bh_r);
    W.hwi_z = 0.5f * wi_z; W.hwh_z = 0.5f * wh_z; W.hb_z = 0.5f * (bi_z + bh_z);
    W.wi_n  = wi_n;        W.bi_n  = bi_n;
    W.hwh_n = 0.5f * wh_n; W.hbh_n = 0.5f * bh_n;

    float h     = 0.0f;
    float val   = 0.0f;
    float nc_r  = W.hb_r;
    float nc_z  = W.hb_z;
    float ghn_h = W.hbh_n;
    float hhalf = 0.0f;

    __syncthreads();
    // cluster-wide: mbarrier init + xs staging visible before any remote op
    asm volatile("barrier.cluster.arrive.aligned;" ::: "memory");
    asm volatile("barrier.cluster.wait.aligned;"   ::: "memory");

    // roles
    const bool mbar_wait   = (rank == 1) && (w == 0);   // cross-CTA consumer
    const bool mbar_pub    = (rank == 0) && (w == 3);   // cross-CTA producer
    const bool remote_sink = mbar_pub;
    const bool bar_pub     = (w < 3);                   // intra-CTA producer

    const float* inbox = (w == 0) ? ((rank == 0) ? xs : xb) : bb[w - 1];
    float*       sink  = (w < 3) ? bb[w] : out;         // G==7 -> out; G==3 remote

    unsigned rem_xb = 0, rem_mbar = 0;
    if (mbar_pub) {
        rem_xb   = mapa_rank(smem_u32(&xb[0]),   1);
        rem_mbar = mapa_rank(smem_u32(&mbar[0]), 1);
    }
    const unsigned mbar_base = smem_u32(&mbar[0]);

    #pragma unroll 1
    for (int ic = 0; ic < 4; ++ic)
        run_chunk<false>(ic, w, lane, l, mbar_wait, bar_pub, mbar_pub, remote_sink,
                         inbox, sink, rem_xb, rem_mbar, mbar_base, out, W,
                         h, val, nc_r, nc_z, ghn_h, hhalf);

    #pragma unroll 1
    for (int ic = 4; ic < 31; ++ic)
        run_chunk<true>(ic, w, lane, l, mbar_wait, bar_pub, mbar_pub, remote_sink,
                        inbox, sink, rem_xb, rem_mbar, mbar_base, out, W,
                        h, val, nc_r, nc_z, ghn_h, hhalf);

    #pragma unroll 1
    for (int ic = 31; ic < NCH; ++ic)
        run_chunk<false>(ic, w, lane, l, mbar_wait, bar_pub, mbar_pub, remote_sink,
                         inbox, sink, rem_xb, rem_mbar, mbar_base, out, W,
                         h, val, nc_r, nc_z, ghn_h, hhalf);

    // no CTA may exit while peers might still target its SMEM
    asm volatile("barrier.cluster.arrive.aligned;" ::: "memory");
    asm volatile("barrier.cluster.wait.aligned;"   ::: "memory");
}

extern "C" void kernel_launch(void* const* d_in, const int* in_sizes, int n_in,
                              void* d_out, int out_size)
{
    const float* X   = (const float*)d_in[0];
    const float* ewi = (const float*)d_in[1];
    const float* ewh = (const float*)d_in[2];
    const float* ebi = (const float*)d_in[3];
    const float* ebh = (const float*)d_in[4];
    const float* dwi = (const float*)d_in[5];
    const float* dwh = (const float*)d_in[6];
    const float* dbi = (const float*)d_in[7];
    const float* dbh = (const float*)d_in[8];
    float* out = (float*)d_out;

    gru_wave_v14<<<2, 128>>>(X, ewi, ewh, ebi, ebh, dwi, dwh, dbi, dbh, out);
}

// round 15
// speedup vs baseline: 1.0140x; 1.0140x over previous
#include <cuda_runtime.h>

// QueryEncDec: 2x128-layer scalar GRU (H=in=1), T=256, fused 256-layer wavefront.
// v14: pipeline split across a 2-CTA CLUSTER (1 warp per SMSP -> no co-warp
// MUFU/issue contention). CTA0 = groups 0-3, CTA1 = groups 4-7.
//  - intra-CTA boundaries: named-barrier rendezvous per 8-step chunk (proven)
//  - cross-CTA boundary (3->4): DSMEM write-once inbox + 32 per-chunk
//    mbarriers (arrive = cluster release, wait = acquire; no parity reuse)
// Rotating shuffle + steady-state specialization retained from v12/v13.
//
// out[0:256]   = dec_out  (layer 255 output at each t)
// out[256:384] = dec_h    (final hidden of global layers 128..255)

#define GRU_T 256
#define KC    8
#define NCH   36     // 36*8 = 288 >= 287 inner steps

__device__ __forceinline__ float ftanh(float a) {
    float r; asm("tanh.approx.f32 %0, %1;" : "=f"(r) : "f"(a)); return r;
}
__device__ __forceinline__ unsigned smem_u32(const void* p) {
    return (unsigned)__cvta_generic_to_shared(p);
}
__device__ __forceinline__ unsigned mapa_rank(unsigned local, int rank) {
    unsigned rem;
    asm("mapa.shared::cluster.u32 %0, %1, %2;" : "=r"(rem) : "r"(local), "r"(rank));
    return rem;
}
__device__ __forceinline__ void st_remote_f32(unsigned addr, float v) {
    asm volatile("st.shared::cluster.f32 [%0], %1;" :: "r"(addr), "f"(v) : "memory");
}
__device__ __forceinline__ void mbar_arrive_remote(unsigned addr) {
    asm volatile("mbarrier.arrive.shared::cluster.b64 _, [%0];" :: "r"(addr) : "memory");
}
__device__ __forceinline__ void mbar_wait_phase0(unsigned addr) {
    asm volatile(
        "{\n\t.reg .pred P;\n"
        "WAITL_%=:\n\t"
        "mbarrier.try_wait.parity.acquire.cluster.shared::cta.b64 P, [%0], %1, 0x989680;\n\t"
        "@!P bra WAITL_%=;\n\t}"
        :: "r"(addr), "r"(0) : "memory");
}

struct GruW {
    float hwi_r, hwh_r, hb_r;
    float hwi_z, hwh_z, hb_z;
    float wi_n,  bi_n,  hwh_n, hbh_n;
};

template<bool STEADY>
__device__ __forceinline__ void run_chunk(
    int ic, int w, int lane, int l,
    bool mbar_wait, bool bar_pub, bool mbar_pub, bool remote_sink,
    const float* __restrict__ inbox, float* __restrict__ sink,
    unsigned rem_xb, unsigned rem_mbar, unsigned mbar_base,
    float* __restrict__ out, const GruW& W,
    float& h, float& val, float& nc_r, float& nc_z, float& ghn_h, float& hhalf)
{
    // ---- consumer side ----
    if (ic < GRU_T / KC) {
        if (mbar_wait) {
            if (lane == 31) mbar_wait_phase0(mbar_base + 8u * ic);
        } else if (w > 0) {
            asm volatile("bar.sync %0, %1;" :: "r"(w), "r"(64) : "memory");
        }
    }
    float pf[KC];
    if (lane == 31 && ic < GRU_T / KC) {
        float4 va = *(const float4*)(inbox + ic * KC);
        float4 vb = *(const float4*)(inbox + ic * KC + 4);
        pf[0]=va.x; pf[1]=va.y; pf[2]=va.z; pf[3]=va.w;
        pf[4]=vb.x; pf[5]=vb.y; pf[6]=vb.z; pf[7]=vb.w;
    }

    const int src = (lane + 31) & 31;      // rotation: lane0 <- lane31

    #pragma unroll
    for (int u = 0; u < KC; ++u) {
        const int j = ic * KC + u;
        const int t = j - lane;

        if (lane == 31) val = pf[u];       // off-chain inbox injection

        const float x = __shfl_sync(0xFFFFFFFFu, val, src, 32);

        const float t_r = ftanh(fmaf(W.hwi_r, x, nc_r));
        const float t_z = ftanh(fmaf(W.hwi_z, x, nc_z));
        const float xn  = fmaf(W.wi_n, x, W.bi_n);
        const float t_n = ftanh(fmaf(ghn_h, t_r, xn + ghn_h));
        const float A   = fmaf(-0.5f, t_z, 0.5f);
        const float C   = fmaf(hhalf, t_z, hhalf);
        const float hn  = fmaf(A, t_n, C);

        val = hn;
        if (STEADY) {
            h = hn;
            if (lane == 31) {
                if (remote_sink) st_remote_f32(rem_xb + 4u * t, h);
                else             sink[t] = h;
            }
        } else {
            const bool valid = (t >= 0) && (t < GRU_T);
            if (valid) h = hn;
            if (lane == 31 && valid) {
                if (remote_sink) st_remote_f32(rem_xb + 4u * t, h);
                else             sink[t] = h;
            }
            if (t == GRU_T - 1 && l >= 128) out[GRU_T + (l - 128)] = h; // dec_h
        }

        nc_r  = fmaf(W.hwh_r, h, W.hb_r);
        nc_z  = fmaf(W.hwh_z, h, W.hb_z);
        ghn_h = fmaf(W.hwh_n, h, W.hbh_n);
        hhalf = 0.5f * h;
    }

    // ---- producer side ----
    if (ic >= 4) {
        if (bar_pub) {
            asm volatile("bar.sync %0, %1;" :: "r"(w + 1), "r"(64) : "memory");
        } else if (mbar_pub) {
            if (lane == 31) mbar_arrive_remote(rem_mbar + 8u * (ic - 4));
        }
    }
}

__global__ __launch_bounds__(128, 1) __cluster_dims__(2, 1, 1)
void gru_wave_v14(const float* __restrict__ X,
                  const float* __restrict__ ewi, const float* __restrict__ ewh,
                  const float* __restrict__ ebi, const float* __restrict__ ebh,
                  const float* __restrict__ dwi, const float* __restrict__ dwh,
                  const float* __restrict__ dbi, const float* __restrict__ dbh,
                  float* __restrict__ out)
{
    const int tid  = threadIdx.x;          // 0..127
    const int w    = tid >> 5;             // local warp 0..3
    const int lane = tid & 31;

    unsigned rank;
    asm("mov.u32 %0, %%cluster_ctarank;" : "=r"(rank));

    const int G = (int)rank * 4 + w;       // global layer group 0..7
    const int l = G * 32 + lane;           // global layer 0..255

    __shared__ __align__(16) float xs[GRU_T];        // X (used by CTA0 g0)
    __shared__ __align__(16) float xb[GRU_T];        // cross-CTA inbox (CTA1)
    __shared__ __align__(16) float bb[3][GRU_T];     // intra-CTA boundaries
    __shared__ __align__(8)  unsigned long long mbar[GRU_T / KC];  // 32

    if (rank == 0) { xs[tid] = X[tid]; xs[tid + 128] = X[tid + 128]; }
    if (tid < GRU_T / KC) {
        unsigned a = smem_u32(&mbar[tid]);
        asm volatile("mbarrier.init.shared.b64 [%0], %1;" :: "r"(a), "r"(1) : "memory");
    }

    // per-layer scalar weights (torch gate order r,z,n)
    const bool  enc = (l < 128);
    const int   li  = enc ? l : (l - 128);
    const float* wi = enc ? ewi : dwi;
    const float* wh = enc ? ewh : dwh;
    const float* bi = enc ? ebi : dbi;
    const float* bh = enc ? ebh : dbh;

    const float wi_r = wi[li*3+0], wi_z = wi[li*3+1], wi_n = wi[li*3+2];
    const float wh_r = wh[li*3+0], wh_z = wh[li*3+1], wh_n = wh[li*3+2];
    const float bi_r = bi[li*3+0], bi_z = bi[li*3+1], bi_n = bi[li*3+2];
    const float bh_r = bh[li*3+0], bh_z = bh[li*3+1], bh_n = bh[li*3+2];

    GruW W;
    W.hwi_r = 0.5f * wi_r; W.hwh_r = 0.5f * wh_r; W.hb_r = 0.5f * (bi_r + bh_r);
    W.hwi_z = 0.5f * wi_z; W.hwh_z = 0.5f * wh_z; W.hb_z = 0.5f * (bi_z + bh_z);
    W.wi_n  = wi_n;        W.bi_n  = bi_n;
    W.hwh_n = 0.5f * wh_n; W.hbh_n = 0.5f * bh_n;

    float h     = 0.0f;
    float val   = 0.0f;
    float nc_r  = W.hb_r;
    float nc_z  = W.hb_z;
    float ghn_h = W.hbh_n;
    float hhalf = 0.0f;

    __syncthreads();
    // cluster-wide: mbarrier init + xs staging visible before any remote op
    asm volatile("barrier.cluster.arrive.aligned;" ::: "memory");
    asm volatile("barrier.cluster.wait.aligned;"   ::: "memory");

    // roles
    const bool mbar_wait   = (rank == 1) && (w == 0);   // cross-CTA consumer
    const bool mbar_pub    = (rank == 0) && (w == 3);   // cross-CTA producer
    const bool remote_sink = mbar_pub;
    const bool bar_pub     = (w < 3);                   // intra-CTA producer

    const float* inbox = (w == 0) ? ((rank == 0) ? xs : xb) : bb[w - 1];
    float*       sink  = (w < 3) ? bb[w] : out;         // G==7 -> out; G==3 remote

    unsigned rem_xb = 0, rem_mbar = 0;
    if (mbar_pub) {
        rem_xb   = mapa_rank(smem_u32(&xb[0]),   1);
        rem_mbar = mapa_rank(smem_u32(&mbar[0]), 1);
    }
    const unsigned mbar_base = smem_u32(&mbar[0]);

    #pragma unroll 1
    for (int ic = 0; ic < 4; ++ic)
        run_chunk<false>(ic, w, lane, l, mbar_wait, bar_pub, mbar_pub, remote_sink,
                         inbox, sink, rem_xb, rem_mbar, mbar_base, out, W,
                         h, val, nc_r, nc_z, ghn_h, hhalf);

    #pragma unroll 1
    for (int ic = 4; ic < 31; ++ic)
        run_chunk<true>(ic, w, lane, l, mbar_wait, bar_pub, mbar_pub, remote_sink,
                        inbox, sink, rem_xb, rem_mbar, mbar_base, out, W,
                        h, val, nc_r, nc_z, ghn_h, hhalf);

    #pragma unroll 1
    for (int ic = 31; ic < NCH; ++ic)
        run_chunk<false>(ic, w, lane, l, mbar_wait, bar_pub, mbar_pub, remote_sink,
                         inbox, sink, rem_xb, rem_mbar, mbar_base, out, W,
                         h, val, nc_r, nc_z, ghn_h, hhalf);

    // no CTA may exit while peers might still target its SMEM
    asm volatile("barrier.cluster.arrive.aligned;" ::: "memory");
    asm volatile("barrier.cluster.wait.aligned;"   ::: "memory");
}

extern "C" void kernel_launch(void* const* d_in, const int* in_sizes, int n_in,
                              void* d_out, int out_size)
{
    const float* X   = (const float*)d_in[0];
    const float* ewi = (const float*)d_in[1];
    const float* ewh = (const float*)d_in[2];
    const float* ebi = (const float*)d_in[3];
    const float* ebh = (const float*)d_in[4];
    const float* dwi = (const float*)d_in[5];
    const float* dwh = (const float*)d_in[6];
    const float* dbi = (const float*)d_in[7];
    const float* dbh = (const float*)d_in[8];
    float* out = (float*)d_out;

    gru_wave_v14<<<2, 128>>>(X, ewi, ewh, ebi, ebh, dwi, dwh, dbi, dbh, out);
}

// round 16
// speedup vs baseline: 1.8606x; 1.8349x over previous
#include <cuda_runtime.h>

// QueryEncDec: 2x128-layer scalar GRU (H=in=1), T=256, fused 256-layer wavefront.
// v15 = v13 (rotating shuffle, steady/generic split, blocking rendezvous,
// priority-reversed warp mapping, unified lane31 sink) + steady-path diet:
// chunk-hoisted sink pointer (no per-step j/t math), tails consume hn directly.
//
// out[0:256]   = dec_out  (layer 255 output at each t)
// out[256:384] = dec_h    (final hidden of global layers 128..255)

#define GRU_T 256
#define NW    8
#define KC    8
#define NCH   36     // 36*8 = 288 >= 287 inner steps

__device__ __forceinline__ float ftanh(float a) {
    float r; asm("tanh.approx.f32 %0, %1;" : "=f"(r) : "f"(a)); return r;
}

struct GruW {
    float hwi_r, hwh_r, hb_r;
    float hwi_z, hwh_z, hb_z;
    float wi_n,  bi_n,  hwh_n, hbh_n;
};

template<bool STEADY>
__device__ __forceinline__ void run_chunk(
    int ic, int g, int lane, int l,
    const float* __restrict__ inbox, float* __restrict__ sink,
    float* __restrict__ out, const GruW& W,
    float& h, float& val, float& nc_r, float& nc_z, float& ghn_h, float& hhalf)
{
    // consumer side of rendezvous (group g waits on bar ID g)
    if (g > 0 && ic < GRU_T / KC) {
        asm volatile("bar.sync %0, %1;" :: "r"(g), "r"(64) : "memory");
    }
    // lane31 prefetches the 8 inbox values for this chunk
    float pf[KC];
    if (lane == 31 && ic < GRU_T / KC) {
        float4 va = *(const float4*)(inbox + ic * KC);
        float4 vb = *(const float4*)(inbox + ic * KC + 4);
        pf[0]=va.x; pf[1]=va.y; pf[2]=va.z; pf[3]=va.w;
        pf[4]=vb.x; pf[5]=vb.y; pf[6]=vb.z; pf[7]=vb.w;
    }

    const int src = (lane + 31) & 31;      // rotation: lane0 <- lane31

    if (STEADY) {
        // all lanes valid (t in [1,247]); lane31 store base hoisted
        float* const sp = sink + (ic * KC - 31);   // lane31: t = ic*8 + u - 31

        #pragma unroll
        for (int u = 0; u < KC; ++u) {
            if (lane == 31) val = pf[u];   // off-chain inbox injection

            const float x = __shfl_sync(0xFFFFFFFFu, val, src, 32);

            const float t_r = ftanh(fmaf(W.hwi_r, x, nc_r));
            const float t_z = ftanh(fmaf(W.hwi_z, x, nc_z));
            const float xn  = fmaf(W.wi_n, x, W.bi_n);
            const float t_n = ftanh(fmaf(ghn_h, t_r, xn + ghn_h));
            const float A   = fmaf(-0.5f, t_z, 0.5f);
            const float C   = fmaf(hhalf, t_z, hhalf);
            const float hn  = fmaf(A, t_n, C);

            val = hn;                       // shuffle source for next step
            if (lane == 31) sp[u] = hn;     // bb[g] for g<7, out (dec_out) for g==7

            nc_r  = fmaf(W.hwh_r, hn, W.hb_r);
            nc_z  = fmaf(W.hwh_z, hn, W.hb_z);
            ghn_h = fmaf(W.hwh_n, hn, W.hbh_n);
            hhalf = 0.5f * hn;
        }
        h = val;                            // restore carried state once
    } else {
        #pragma unroll
        for (int u = 0; u < KC; ++u) {
            const int j = ic * KC + u;
            const int t = j - lane;

            if (lane == 31) val = pf[u];

            const float x = __shfl_sync(0xFFFFFFFFu, val, src, 32);

            const float t_r = ftanh(fmaf(W.hwi_r, x, nc_r));
            const float t_z = ftanh(fmaf(W.hwi_z, x, nc_z));
            const float xn  = fmaf(W.wi_n, x, W.bi_n);
            const float t_n = ftanh(fmaf(ghn_h, t_r, xn + ghn_h));
            const float A   = fmaf(-0.5f, t_z, 0.5f);
            const float C   = fmaf(hhalf, t_z, hhalf);
            const float hn  = fmaf(A, t_n, C);

            val = hn;
            const bool valid = (t >= 0) && (t < GRU_T);
            if (valid) h = hn;
            if (lane == 31 && valid) sink[t] = h;
            if (t == GRU_T - 1 && l >= 128) out[GRU_T + (l - 128)] = h; // dec_h

            nc_r  = fmaf(W.hwh_r, h, W.hb_r);
            nc_z  = fmaf(W.hwh_z, h, W.hb_z);
            ghn_h = fmaf(W.hwh_n, h, W.hbh_n);
            hhalf = 0.5f * h;
        }
        val = h;   // keep rotation source consistent with carried state
    }

    // producer side of rendezvous (group g publishes on bar ID g+1; blocking,
    // skew-safe; BAR drains the chunk's STS)
    if (g < NW - 1 && ic >= 4) {
        asm volatile("bar.sync %0, %1;" :: "r"(g + 1), "r"(64) : "memory");
    }
}

__global__ __launch_bounds__(256, 1)
void gru_wave_v15(const float* __restrict__ X,
                  const float* __restrict__ ewi, const float* __restrict__ ewh,
                  const float* __restrict__ ebi, const float* __restrict__ ebh,
                  const float* __restrict__ dwi, const float* __restrict__ dwh,
                  const float* __restrict__ dbi, const float* __restrict__ dbh,
                  float* __restrict__ out)
{
    const int tid  = threadIdx.x;
    const int w    = tid >> 5;
    const int lane = tid & 31;
    const int g    = (NW - 1) - w;         // upstream group on highest wid
    const int l    = g * 32 + lane;        // global layer 0..255

    __shared__ __align__(16) float xs[GRU_T];
    __shared__ __align__(16) float bb[NW - 1][GRU_T];

    if (tid < GRU_T) xs[tid] = X[tid];

    // per-layer scalar weights (torch gate order r,z,n)
    const bool  enc = (l < 128);
    const int   li  = enc ? l : (l - 128);
    const float* wi = enc ? ewi : dwi;
    const float* wh = enc ? ewh : dwh;
    const float* bi = enc ? ebi : dbi;
    const float* bh = enc ? ebh : dbh;

    const float wi_r = wi[li*3+0], wi_z = wi[li*3+1], wi_n = wi[li*3+2];
    const float wh_r = wh[li*3+0], wh_z = wh[li*3+1], wh_n = wh[li*3+2];
    const float bi_r = bi[li*3+0], bi_z = bi[li*3+1], bi_n = bi[li*3+2];
    const float bh_r = bh[li*3+0], bh_z = bh[li*3+1], bh_n = bh[li*3+2];

    GruW W;
    W.hwi_r = 0.5f * wi_r; W.hwh_r = 0.5f * wh_r; W.hb_r = 0.5f * (bi_r + bh_r);
    W.hwi_z = 0.5f * wi_z; W.hwh_z = 0.5f * wh_z; W.hb_z = 0.5f * (bi_z + bh_z);
    W.wi_n  = wi_n;        W.bi_n  = bi_n;
    W.hwh_n = 0.5f * wh_n; W.hbh_n = 0.5f * bh_n;

    float h     = 0.0f;
    float val   = 0.0f;
    float nc_r  = W.hb_r;
    float nc_z  = W.hb_z;
    float ghn_h = W.hbh_n;
    float hhalf = 0.0f;

    __syncthreads();

    const float* inbox = (g == 0) ? xs : bb[g - 1];
    float*       sink  = (g < NW - 1) ? bb[g] : out;   // lane31 writes here

    #pragma unroll 1
    for (int ic = 0; ic < 4; ++ic)
        run_chunk<false>(ic, g, lane, l, inbox, sink, out, W,
                         h, val, nc_r, nc_z, ghn_h, hhalf);

    #pragma unroll 1
    for (int ic = 4; ic < 31; ++ic)
        run_chunk<true>(ic, g, lane, l, inbox, sink, out, W,
                        h, val, nc_r, nc_z, ghn_h, hhalf);

    #pragma unroll 1
    for (int ic = 31; ic < NCH; ++ic)
        run_chunk<false>(ic, g, lane, l, inbox, sink, out, W,
                         h, val, nc_r, nc_z, ghn_h, hhalf);
}

extern "C" void kernel_launch(void* const* d_in, const int* in_sizes, int n_in,
                              void* d_out, int out_size)
{
    const float* X   = (const float*)d_in[0];
    const float* ewi = (const float*)d_in[1];
    const float* ewh = (const float*)d_in[2];
    const float* ebi = (const float*)d_in[3];
    const float* ebh = (const float*)d_in[4];
    const float* dwi = (const float*)d_in[5];
    const float* dwh = (const float*)d_in[6];
    const float* dbi = (const float*)d_in[7];
    const float* dbh = (const float*)d_in[8];
    float* out = (float*)d_out;

    gru_wave_v15<<<1, 256>>>(X, ewi, ewh, ebi, ebh, dwi, dwh, dbi, dbh, out);
}

// round 17
// speedup vs baseline: 1.9370x; 1.0411x over previous
#include <cuda_runtime.h>

// QueryEncDec: 2x128-layer scalar GRU (H=in=1), T=256, fused 256-layer wavefront.
// v16 = v15 + (a) producer publish moved between u=6 and u=7 (t-chunk ic-4 is
// complete at end of u=6: last value = lane31's u=6 store), releasing each
// consumer one step earlier; (b) steady-path lane31 sink stores batched into
// float2 pairs (u1,u2)(u3,u4)(u5,u6) -- 8B-aligned since t(odd u) is even.
//
// out[0:256]   = dec_out  (layer 255 output at each t)
// out[256:384] = dec_h    (final hidden of global layers 128..255)

#define GRU_T 256
#define NW    8
#define KC    8
#define NCH   36     // 36*8 = 288 >= 287 inner steps

__device__ __forceinline__ float ftanh(float a) {
    float r; asm("tanh.approx.f32 %0, %1;" : "=f"(r) : "f"(a)); return r;
}

struct GruW {
    float hwi_r, hwh_r, hb_r;
    float hwi_z, hwh_z, hb_z;
    float wi_n,  bi_n,  hwh_n, hbh_n;
};

// one GRU cell step (x -> hn), tails updated from hn
__device__ __forceinline__ float cell(const GruW& W, float x,
                                      float& nc_r, float& nc_z,
                                      float& ghn_h, float& hhalf)
{
    const float t_r = ftanh(fmaf(W.hwi_r, x, nc_r));
    const float t_z = ftanh(fmaf(W.hwi_z, x, nc_z));
    const float xn  = fmaf(W.wi_n, x, W.bi_n);
    const float t_n = ftanh(fmaf(ghn_h, t_r, xn + ghn_h));
    const float A   = fmaf(-0.5f, t_z, 0.5f);
    const float C   = fmaf(hhalf, t_z, hhalf);
    return fmaf(A, t_n, C);
}

__device__ __forceinline__ void tails(const GruW& W, float hn,
                                      float& nc_r, float& nc_z,
                                      float& ghn_h, float& hhalf)
{
    nc_r  = fmaf(W.hwh_r, hn, W.hb_r);
    nc_z  = fmaf(W.hwh_z, hn, W.hb_z);
    ghn_h = fmaf(W.hwh_n, hn, W.hbh_n);
    hhalf = 0.5f * hn;
}

template<bool STEADY>
__device__ __forceinline__ void run_chunk(
    int ic, int g, int lane, int l,
    const float* __restrict__ inbox, float* __restrict__ sink,
    float* __restrict__ out, const GruW& W,
    float& h, float& val, float& nc_r, float& nc_z, float& ghn_h, float& hhalf)
{
    // consumer side of rendezvous (group g waits on bar ID g)
    if (g > 0 && ic < GRU_T / KC) {
        asm volatile("bar.sync %0, %1;" :: "r"(g), "r"(64) : "memory");
    }
    // lane31 prefetches the 8 inbox values for this chunk
    float pf[KC];
    if (lane == 31 && ic < GRU_T / KC) {
        float4 va = *(const float4*)(inbox + ic * KC);
        float4 vb = *(const float4*)(inbox + ic * KC + 4);
        pf[0]=va.x; pf[1]=va.y; pf[2]=va.z; pf[3]=va.w;
        pf[4]=vb.x; pf[5]=vb.y; pf[6]=vb.z; pf[7]=vb.w;
    }

    const int src = (lane + 31) & 31;      // rotation: lane0 <- lane31

    if (STEADY) {
        // all lanes valid (t in [1,247]); lane31 store base hoisted
        float* const sp = sink + (ic * KC - 31);   // lane31: t = ic*8 + u - 31
        float hn_prev = 0.0f;

        #pragma unroll
        for (int u = 0; u < 7; ++u) {
            if (lane == 31) val = pf[u];   // off-chain inbox injection
            const float x  = __shfl_sync(0xFFFFFFFFu, val, src, 32);
            const float hn = cell(W, x, nc_r, nc_z, ghn_h, hhalf);
            val = hn;
            if (lane == 31) {
                if (u == 0)      sp[0] = hn;                     // scalar
                else if (u & 1)  hn_prev = hn;                   // u=1,3,5
                else {                                           // u=2,4,6
                    float2 v; v.x = hn_prev; v.y = hn;
                    *(float2*)(sp + (u - 1)) = v;                // t even -> 8B ok
                }
            }
            tails(W, hn, nc_r, nc_z, ghn_h, hhalf);
        }

        // producer publish: t-chunk ic-4 complete at end of u=6 (t=8ic-25)
        if (g < NW - 1) {
            asm volatile("bar.sync %0, %1;" :: "r"(g + 1), "r"(64) : "memory");
        }

        {   // u = 7
            if (lane == 31) val = pf[7];
            const float x  = __shfl_sync(0xFFFFFFFFu, val, src, 32);
            const float hn = cell(W, x, nc_r, nc_z, ghn_h, hhalf);
            val = hn;
            if (lane == 31) sp[7] = hn;
            tails(W, hn, nc_r, nc_z, ghn_h, hhalf);
        }
        h = val;
    } else {
        #pragma unroll
        for (int u = 0; u < KC; ++u) {
            const int j = ic * KC + u;
            const int t = j - lane;

            if (lane == 31) val = pf[u];
            const float x  = __shfl_sync(0xFFFFFFFFu, val, src, 32);
            const float hn = cell(W, x, nc_r, nc_z, ghn_h, hhalf);

            val = hn;
            const bool valid = (t >= 0) && (t < GRU_T);
            if (valid) h = hn;
            if (lane == 31 && valid) sink[t] = h;
            if (t == GRU_T - 1 && l >= 128) out[GRU_T + (l - 128)] = h; // dec_h

            tails(W, h, nc_r, nc_z, ghn_h, hhalf);

            // publish between u=6 and u=7 (same position as steady path)
            if (u == 6 && g < NW - 1 && ic >= 4) {
                asm volatile("bar.sync %0, %1;" :: "r"(g + 1), "r"(64) : "memory");
            }
        }
        val = h;   // keep rotation source consistent with carried state
    }
}

__global__ __launch_bounds__(256, 1)
void gru_wave_v16(const float* __restrict__ X,
                  const float* __restrict__ ewi, const float* __restrict__ ewh,
                  const float* __restrict__ ebi, const float* __restrict__ ebh,
                  const float* __restrict__ dwi, const float* __restrict__ dwh,
                  const float* __restrict__ dbi, const float* __restrict__ dbh,
                  float* __restrict__ out)
{
    const int tid  = threadIdx.x;
    const int w    = tid >> 5;
    const int lane = tid & 31;
    const int g    = (NW - 1) - w;         // upstream group on highest wid
    const int l    = g * 32 + lane;        // global layer 0..255

    __shared__ __align__(16) float xs[GRU_T];
    __shared__ __align__(16) float bb[NW - 1][GRU_T];

    if (tid < GRU_T) xs[tid] = X[tid];

    // per-layer scalar weights (torch gate order r,z,n)
    const bool  enc = (l < 128);
    const int   li  = enc ? l : (l - 128);
    const float* wi = enc ? ewi : dwi;
    const float* wh = enc ? ewh : dwh;
    const float* bi = enc ? ebi : dbi;
    const float* bh = enc ? ebh : dbh;

    const float wi_r = wi[li*3+0], wi_z = wi[li*3+1], wi_n = wi[li*3+2];
    const float wh_r = wh[li*3+0], wh_z = wh[li*3+1], wh_n = wh[li*3+2];
    const float bi_r = bi[li*3+0], bi_z = bi[li*3+1], bi_n = bi[li*3+2];
    const float bh_r = bh[li*3+0], bh_z = bh[li*3+1], bh_n = bh[li*3+2];

    GruW W;
    W.hwi_r = 0.5f * wi_r; W.hwh_r = 0.5f * wh_r; W.hb_r = 0.5f * (bi_r + bh_r);
    W.hwi_z = 0.5f * wi_z; W.hwh_z = 0.5f * wh_z; W.hb_z = 0.5f * (bi_z + bh_z);
    W.wi_n  = wi_n;        W.bi_n  = bi_n;
    W.hwh_n = 0.5f * wh_n; W.hbh_n = 0.5f * bh_n;

    float h     = 0.0f;
    float val   = 0.0f;
    float nc_r  = W.hb_r;
    float nc_z  = W.hb_z;
    float ghn_h = W.hbh_n;
    float hhalf = 0.0f;

    __syncthreads();

    const float* inbox = (g == 0) ? xs : bb[g - 1];
    float*       sink  = (g < NW - 1) ? bb[g] : out;   // lane31 writes here

    #pragma unroll 1
    for (int ic = 0; ic < 4; ++ic)
        run_chunk<false>(ic, g, lane, l, inbox, sink, out, W,
                         h, val, nc_r, nc_z, ghn_h, hhalf);

    #pragma unroll 1
    for (int ic = 4; ic < 31; ++ic)
        run_chunk<true>(ic, g, lane, l, inbox, sink, out, W,
                        h, val, nc_r, nc_z, ghn_h, hhalf);

    #pragma unroll 1
    for (int ic = 31; ic < NCH; ++ic)
        run_chunk<false>(ic, g, lane, l, inbox, sink, out, W,
                         h, val, nc_r, nc_z, ghn_h, hhalf);
}

extern "C" void kernel_launch(void* const* d_in, const int* in_sizes, int n_in,
                              void* d_out, int out_size)
{
    const float* X   = (const float*)d_in[0];
    const float* ewi = (const float*)d_in[1];
    const float* ewh = (const float*)d_in[2];
    const float* ebi = (const float*)d_in[3];
    const float* ebh = (const float*)d_in[4];
    const float* dwi = (const float*)d_in[5];
    const float* dwh = (const float*)d_in[6];
    const float* dbi = (const float*)d_in[7];
    const float* dbh = (const float*)d_in[8];
    float* out = (float*)d_out;

    gru_wave_v16<<<1, 256>>>(X, ewi, ewh, ebi, ebh, dwi, dwh, dbi, dbh, out);
}